// round 15
// baseline (speedup 1.0000x reference)
#include <cuda_runtime.h>

#define NN 50000
#define EE 800000
#define HH 128
#define LL 3
#define GG 64
#define BN_EPS 1e-5f
#define SCAN_CH 196

// ---------------- scratch (device globals) ----------------
__device__ __align__(16) float g_y0[NN * HH];
__device__ __align__(16) float g_y1[NN * HH];
__device__ __align__(16) float g_agg[NN * HH];
__device__ __align__(16) float g_Wt[LL * 2 * HH * HH];   // [l][k(0..255)][o] pre-transposed
__device__ __align__(16) float g_Ws[2 * HH * HH];        // affine-folded weights, current layer
__device__ __align__(16) float g_bias[HH];               // folded bias, current layer
__device__ int   g_rowptr[NN + 1];
__device__ int   g_colidx[EE];
__device__ int   g_cnt[NN];
__device__ float g_invdeg[NN];
__device__ int   g_part[256];
__device__ int   g_base[256];
__device__ __align__(16) float g_sum[2][HH];             // BN stats, double-buffered by parity
__device__ __align__(16) float g_sumsq[2][HH];
__device__ __align__(16) float g_fcs[HH];
__device__ float g_c0;
__device__ float g_pool[GG];

// ---------------- helpers ----------------
__device__ __forceinline__ const float* sel_h(const float* x, int s) {
    return (s == 0) ? x : ((s == 1) ? g_y0 : g_y1);
}

// BN affine coefs of layer (layer-1), read from parity (layer+1)&1. layer==0 -> identity.
__device__ __forceinline__ void get_coef(int layer, const float* gamma, const float* beta,
                                         int c, float& a, float& b) {
    if (layer == 0) { a = 1.f; b = 0.f; return; }
    int p = (layer + 1) & 1;
    float mean = g_sum[p][c] * (1.0f / NN);
    float var  = g_sumsq[p][c] * (1.0f / NN) - mean * mean;
    a = gamma[c] * rsqrtf(var + BN_EPS);
    b = beta[c] - mean * a;
}

// packed dual-FMA: d.lo += a.lo*b.lo ; d.hi += a.hi*b.hi
__device__ __forceinline__ void ffma2(float2& d, const float2& a, const float2& b) {
    asm("fma.rn.f32x2 %0, %1, %2, %0;"
        : "+l"(reinterpret_cast<unsigned long long&>(d))
        : "l"(reinterpret_cast<const unsigned long long&>(a)),
          "l"(reinterpret_cast<const unsigned long long&>(b)));
}

__device__ __forceinline__ void add4(float4& a, const float4& v) {
    a.x += v.x; a.y += v.y; a.z += v.z; a.w += v.w;
}

// ---------------- setup kernels ----------------
__global__ void zero_init_kernel() {
    int i = blockIdx.x * blockDim.x + threadIdx.x;
    if (i < NN) g_cnt[i] = 0;
    if (i < GG) g_pool[i] = 0.f;
}

__global__ void count_kernel(const int* __restrict__ dst) {
    int i = blockIdx.x * blockDim.x + threadIdx.x;
    if (i < EE) atomicAdd(&g_cnt[dst[i]], 1);
}

__global__ void scan1_kernel() {
    __shared__ int s[256];
    int b = blockIdx.x, t = threadIdx.x;
    int idx = b * SCAN_CH + t;
    s[t] = (t < SCAN_CH && idx < NN) ? g_cnt[idx] : 0;
    __syncthreads();
    for (int off = 128; off; off >>= 1) {
        if (t < off) s[t] += s[t + off];
        __syncthreads();
    }
    if (t == 0) g_part[b] = s[0];
}

__global__ void scan2_kernel() {
    __shared__ int s[256];
    int t = threadIdx.x;
    s[t] = g_part[t];
    __syncthreads();
    int acc = s[t];
    for (int off = 1; off < 256; off <<= 1) {
        int v = 0;
        if (t >= off) v = s[t - off];
        __syncthreads();
        s[t] += v;
        __syncthreads();
    }
    g_base[t] = s[t] - acc;
}

__global__ void scan3_kernel() {
    __shared__ int s[256];
    int b = blockIdx.x, t = threadIdx.x;
    int idx = b * SCAN_CH + t;
    int c = (t < SCAN_CH && idx < NN) ? g_cnt[idx] : 0;
    s[t] = c;
    __syncthreads();
    int own = s[t];
    for (int off = 1; off < 256; off <<= 1) {
        int v = 0;
        if (t >= off) v = s[t - off];
        __syncthreads();
        s[t] += v;
        __syncthreads();
    }
    if (t < SCAN_CH && idx < NN) {
        g_rowptr[idx] = g_base[b] + s[t] - own;
        g_invdeg[idx] = 1.0f / (float)(c > 1 ? c : 1);
        g_cnt[idx] = 0;
    }
    if (b == 0 && t == 0) g_rowptr[NN] = EE;
}

__global__ void fill_kernel(const int* __restrict__ src,
                            const int* __restrict__ dst) {
    int i = blockIdx.x * blockDim.x + threadIdx.x;
    if (i >= EE) return;
    int d = dst[i];
    int pos = g_rowptr[d] + atomicAdd(&g_cnt[d], 1);
    g_colidx[pos] = src[i];
}

__global__ void transW_kernel(const float* __restrict__ wl,
                              const float* __restrict__ wr) {
    int idx = blockIdx.x * blockDim.x + threadIdx.x;
    if (idx >= LL * 2 * HH * HH) return;
    int l = idx / (2 * HH * HH);
    int rem = idx % (2 * HH * HH);
    int k = rem / HH;
    int o = rem % HH;
    float v = (k < HH) ? wl[(l * HH + o) * HH + k]
                       : wr[(l * HH + o) * HH + (k - HH)];
    g_Wt[idx] = v;
}

// ---------------- per-layer kernels ----------------
// blocks 0..6249: mean aggregation (with prev BN affine folded in), 4-way unrolled gather.
// blocks 6250..6377: fold prev affine into this layer's weights.
// block 6378: fold bias; zero BN stats for this layer.
#define AGG_BLOCKS ((NN * 32 + 255) / 256)   // 6250
__global__ void agg_prep_kernel(const float* __restrict__ x, int sel, int layer,
                                const float* __restrict__ bias,
                                const float* __restrict__ gammaP,
                                const float* __restrict__ betaP) {
    int b = blockIdx.x;
    int tid = threadIdx.x;
    if (b >= AGG_BLOCKS) {
        int wb = b - AGG_BLOCKS;
        if (wb < 128) {
            int idx = wb * 256 + tid;
            int k = idx >> 7;
            float s = 1.f;
            if (k >= HH) {
                float a, bb;
                get_coef(layer, gammaP, betaP, k - HH, a, bb);
                s = a;
            }
            g_Ws[idx] = s * g_Wt[layer * 2 * HH * HH + idx];
        } else {
            __shared__ float cb[HH];
            if (tid < HH) {
                float a, bb;
                get_coef(layer, gammaP, betaP, tid, a, bb);
                cb[tid] = bb;
                g_sum[layer & 1][tid] = 0.f;
                g_sumsq[layer & 1][tid] = 0.f;
            }
            __syncthreads();
            if (tid < HH) {
                float s = bias[tid];
                const float* w = g_Wt + layer * 2 * HH * HH + HH * HH;
                for (int k = 0; k < HH; k++) s += cb[k] * w[k * HH + tid];
                g_bias[tid] = s;
            }
        }
        return;
    }
    int t = b * 256 + tid;
    int node = t >> 5;
    int lane = t & 31;
    if (node >= NN) return;
    const float4* __restrict__ h4 = (const float4*)sel_h(x, sel);
    const int* __restrict__ ci = g_colidx;
    float4 a0 = make_float4(0.f, 0.f, 0.f, 0.f);
    float4 a1 = make_float4(0.f, 0.f, 0.f, 0.f);
    float4 a2 = make_float4(0.f, 0.f, 0.f, 0.f);
    float4 a3 = make_float4(0.f, 0.f, 0.f, 0.f);
    int e0 = g_rowptr[node];
    int e1 = g_rowptr[node + 1];
    int j = e0;
    for (; j + 3 < e1; j += 4) {
        int s0 = ci[j], s1 = ci[j + 1], s2 = ci[j + 2], s3 = ci[j + 3];
        float4 v0 = h4[s0 * 32 + lane];
        float4 v1 = h4[s1 * 32 + lane];
        float4 v2 = h4[s2 * 32 + lane];
        float4 v3 = h4[s3 * 32 + lane];
        add4(a0, v0); add4(a1, v1); add4(a2, v2); add4(a3, v3);
    }
    for (; j < e1; j++) add4(a0, h4[ci[j] * 32 + lane]);
    a0.x += a1.x + a2.x + a3.x;
    a0.y += a1.y + a2.y + a3.y;
    a0.z += a1.z + a2.z + a3.z;
    a0.w += a1.w + a2.w + a3.w;
    float4 o = make_float4(0.f, 0.f, 0.f, 0.f);
    if (e1 > e0) {
        float inv = g_invdeg[node];
        float c0a, c0b, c1a, c1b, c2a, c2b, c3a, c3b;
        get_coef(layer, gammaP, betaP, lane * 4 + 0, c0a, c0b);
        get_coef(layer, gammaP, betaP, lane * 4 + 1, c1a, c1b);
        get_coef(layer, gammaP, betaP, lane * 4 + 2, c2a, c2b);
        get_coef(layer, gammaP, betaP, lane * 4 + 3, c3a, c3b);
        o = make_float4(fmaf(c0a, a0.x * inv, c0b), fmaf(c1a, a0.y * inv, c1b),
                        fmaf(c2a, a0.z * inv, c2b), fmaf(c3a, a0.w * inv, c3b));
    }
    ((float4*)g_agg)[node * 32 + lane] = o;
}

// y = relu(agg @ Wl^T + bias' + h_raw @ Wr_scaled^T), fused BN column sums.
// 64x128 tile / 128 threads / 8x8 per thread; K=256, 16 chunks. (R7 config, occ 5)
__global__ void __launch_bounds__(128, 5)
gemm_kernel(const float* __restrict__ x, int sel, int outsel, int par) {
    __shared__ float As[16 * 64];    // A tile transposed: As[kk][row]
    __shared__ float Bs[16 * 128];   // W tile: Bs[kk][out]
    __shared__ float ssum[128];
    __shared__ float ssq[128];

    const int tid = threadIdx.x;
    const int tx = tid & 15;
    const int ty = tid >> 4;         // 0..7
    const int row0 = blockIdx.x * 64;

    const float* hin = sel_h(x, sel);
    float* yout = (outsel == 0) ? g_y0 : g_y1;

    float2 acc[4][8];   // row-pairs x 8 cols
    {
        float bc[8];
        #pragma unroll
        for (int j = 0; j < 4; j++) {
            bc[j]     = g_bias[tx * 4 + j];
            bc[4 + j] = g_bias[64 + tx * 4 + j];
        }
        #pragma unroll
        for (int i2 = 0; i2 < 4; i2++)
            #pragma unroll
            for (int j = 0; j < 8; j++) acc[i2][j] = make_float2(bc[j], bc[j]);
    }

    for (int chunk = 0; chunk < 16; chunk++) {
        // stage W tile: 16 k-rows x 128 outs (512 float4s / 128 threads)
        {
            const float4* w4 = (const float4*)(g_Ws + chunk * 16 * HH);
            float4* bs4 = (float4*)Bs;
            #pragma unroll
            for (int i = 0; i < 4; i++) bs4[tid + i * 128] = w4[tid + i * 128];
        }
        // stage A tile: 64 rows x 16 k, transposed (256 float4s / 128 threads)
        {
            const float4* src4 = (const float4*)((chunk < 8) ? g_agg : hin);
            const int cseg = (chunk & 7) * 4;
            #pragma unroll
            for (int i = 0; i < 2; i++) {
                int idx = tid + i * 128;
                int r = idx >> 2, seg = idx & 3;
                int row = row0 + r;
                float4 v = make_float4(0.f, 0.f, 0.f, 0.f);
                if (row < NN) v = src4[row * 32 + cseg + seg];
                As[(seg * 4 + 0) * 64 + r] = v.x;
                As[(seg * 4 + 1) * 64 + r] = v.y;
                As[(seg * 4 + 2) * 64 + r] = v.z;
                As[(seg * 4 + 3) * 64 + r] = v.w;
            }
        }
        __syncthreads();
        #pragma unroll
        for (int kk = 0; kk < 16; kk++) {
            float4 a0 = *(const float4*)&As[kk * 64 + ty * 4];
            float4 a1 = *(const float4*)&As[kk * 64 + 32 + ty * 4];
            float4 b0 = *(const float4*)&Bs[kk * 128 + tx * 4];
            float4 b1 = *(const float4*)&Bs[kk * 128 + 64 + tx * 4];
            float2 ap[4] = {{a0.x, a0.y}, {a0.z, a0.w}, {a1.x, a1.y}, {a1.z, a1.w}};
            float  bj[8] = {b0.x, b0.y, b0.z, b0.w, b1.x, b1.y, b1.z, b1.w};
            #pragma unroll
            for (int j = 0; j < 8; j++) {
                float2 bb = make_float2(bj[j], bj[j]);
                #pragma unroll
                for (int i2 = 0; i2 < 4; i2++) ffma2(acc[i2][j], ap[i2], bb);
            }
        }
        __syncthreads();
    }

    // epilogue: relu, store, BN column sums
    float csum[8], csq[8];
    #pragma unroll
    for (int j = 0; j < 8; j++) { csum[j] = 0.f; csq[j] = 0.f; }
    #pragma unroll
    for (int i2 = 0; i2 < 4; i2++) {
        int rbase = (i2 < 2) ? (row0 + ty * 4 + i2 * 2)
                             : (row0 + 32 + ty * 4 + (i2 - 2) * 2);
        #pragma unroll
        for (int half = 0; half < 2; half++) {
            int r = rbase + half;
            if (r < NN) {
                float v[8];
                #pragma unroll
                for (int j = 0; j < 8; j++) {
                    float raw = half ? acc[i2][j].y : acc[i2][j].x;
                    v[j] = fmaxf(raw, 0.f);
                    csum[j] += v[j];
                    csq[j]  += v[j] * v[j];
                }
                float4* y4 = (float4*)(yout + r * HH);
                y4[tx]      = make_float4(v[0], v[1], v[2], v[3]);
                y4[16 + tx] = make_float4(v[4], v[5], v[6], v[7]);
            }
        }
    }
    ssum[tid] = 0.f; ssq[tid] = 0.f;
    __syncthreads();
    #pragma unroll
    for (int j = 0; j < 4; j++) {
        atomicAdd(&ssum[tx * 4 + j],      csum[j]);
        atomicAdd(&ssq[tx * 4 + j],       csq[j]);
        atomicAdd(&ssum[64 + tx * 4 + j], csum[4 + j]);
        atomicAdd(&ssq[64 + tx * 4 + j],  csq[4 + j]);
    }
    __syncthreads();
    atomicAdd(&g_sum[par][tid],   ssum[tid]);
    atomicAdd(&g_sumsq[par][tid], ssq[tid]);
}

// fold last layer's affine into the FC: fcs = a .* fcw ; c0 = sum(b .* fcw)
__global__ void fcprep_kernel(const float* __restrict__ fcw,
                              const float* __restrict__ gammaP,
                              const float* __restrict__ betaP) {
    __shared__ float red[128];
    int c = threadIdx.x;
    float w = fcw[c];
    float a, b;
    get_coef(LL, gammaP, betaP, c, a, b);
    g_fcs[c] = a * w;
    red[c] = b * w;
    __syncthreads();
    for (int off = 64; off; off >>= 1) {
        if (c < off) red[c] += red[c + off];
        __syncthreads();
    }
    if (c == 0) g_c0 = red[0];
}

__global__ void pool_kernel(const int* __restrict__ batch) {
    int t = blockIdx.x * blockDim.x + threadIdx.x;
    int node = t >> 5;
    int lane = t & 31;
    if (node >= NN) return;
    float4 v = ((const float4*)g_y0)[node * 32 + lane];
    float4 w = ((const float4*)g_fcs)[lane];
    float s = v.x * w.x + v.y * w.y + v.z * w.z + v.w * w.w;
    #pragma unroll
    for (int off = 16; off; off >>= 1) s += __shfl_down_sync(0xffffffffu, s, off);
    if (lane == 0) atomicAdd(&g_pool[batch[node]], s + g_c0);
}

__global__ void final_kernel(const float* __restrict__ fcb, float* __restrict__ out) {
    int g = threadIdx.x;
    if (g < GG) {
        float z = g_pool[g] + fcb[0];
        out[g] = 1.0f / (1.0f + expf(-z));
    }
}

// ---------------- launch ----------------
extern "C" void kernel_launch(void* const* d_in, const int* in_sizes, int n_in,
                              void* d_out, int out_size) {
    const float* x       = (const float*)d_in[0];
    const int*   ei      = (const int*)d_in[1];
    const int*   src     = ei;
    const int*   dst     = ei + EE;
    const int*   batch   = (const int*)d_in[3];
    const float* lin_l_w = (const float*)d_in[4];
    const float* lin_l_b = (const float*)d_in[5];
    const float* lin_r_w = (const float*)d_in[6];
    const float* gamma   = (const float*)d_in[7];
    const float* beta    = (const float*)d_in[8];
    const float* fcw     = (const float*)d_in[9];
    const float* fcb     = (const float*)d_in[10];
    float*       out     = (float*)d_out;

    zero_init_kernel<<<(NN + 255) / 256, 256>>>();
    count_kernel<<<(EE + 255) / 256, 256>>>(dst);
    scan1_kernel<<<256, 256>>>();
    scan2_kernel<<<1, 256>>>();
    scan3_kernel<<<256, 256>>>();
    fill_kernel<<<(EE + 255) / 256, 256>>>(src, dst);
    transW_kernel<<<(LL * 2 * HH * HH + 255) / 256, 256>>>(lin_l_w, lin_r_w);

    for (int l = 0; l < LL; l++) {
        int sel    = (l == 0) ? 0 : ((l == 1) ? 1 : 2);   // x, g_y0, g_y1
        int outsel = (l == 1) ? 1 : 0;                    // y0, y1, y0
        const float* gp = gamma + (l > 0 ? (l - 1) * HH : 0);
        const float* bp = beta  + (l > 0 ? (l - 1) * HH : 0);
        agg_prep_kernel<<<AGG_BLOCKS + 129, 256>>>(x, sel, l, lin_l_b + l * HH, gp, bp);
        gemm_kernel<<<(NN + 63) / 64, 128>>>(x, sel, outsel, l & 1);
    }

    fcprep_kernel<<<1, 128>>>(fcw, gamma + 2 * HH, beta + 2 * HH);
    pool_kernel<<<(NN * 32 + 255) / 256, 256>>>(batch);
    final_kernel<<<1, 64>>>(fcb, out);
}

// round 16
// speedup vs baseline: 1.4836x; 1.4836x over previous
#include <cuda_runtime.h>

#define NN 50000
#define EE 800000
#define HH 128
#define LL 3
#define GG 64
#define BN_EPS 1e-5f
#define SCAN_CH 196

// ---------------- scratch (device globals) ----------------
__device__ __align__(16) float g_y0[NN * HH];
__device__ __align__(16) float g_y1[NN * HH];
__device__ __align__(16) float g_agg[NN * HH];
__device__ __align__(16) float g_Wt[LL * 2 * HH * HH];   // [l][k(0..255)][o] pre-transposed
__device__ __align__(16) float g_Ws[2 * HH * HH];        // affine-folded weights, current layer
__device__ __align__(16) float g_bias[HH];               // folded bias, current layer
__device__ int   g_rowptr[NN + 1];
__device__ int   g_colidx[EE];
__device__ int   g_cnt[NN];
__device__ float g_invdeg[NN];
__device__ int   g_part[256];
__device__ int   g_base[256];
__device__ __align__(16) float g_sum[2][HH];             // BN stats, double-buffered by parity
__device__ __align__(16) float g_sumsq[2][HH];
__device__ __align__(16) float g_fcs[HH];
__device__ float g_c0;
__device__ float g_pool[GG];

// ---------------- helpers ----------------
__device__ __forceinline__ const float* sel_h(const float* x, int s) {
    return (s == 0) ? x : ((s == 1) ? g_y0 : g_y1);
}

// BN affine coefs of layer (layer-1), read from parity (layer+1)&1. layer==0 -> identity.
__device__ __forceinline__ void get_coef(int layer, const float* gamma, const float* beta,
                                         int c, float& a, float& b) {
    if (layer == 0) { a = 1.f; b = 0.f; return; }
    int p = (layer + 1) & 1;
    float mean = g_sum[p][c] * (1.0f / NN);
    float var  = g_sumsq[p][c] * (1.0f / NN) - mean * mean;
    a = gamma[c] * rsqrtf(var + BN_EPS);
    b = beta[c] - mean * a;
}

// packed dual-FMA: d.lo += a.lo*b.lo ; d.hi += a.hi*b.hi
__device__ __forceinline__ void ffma2(float2& d, const float2& a, const float2& b) {
    asm("fma.rn.f32x2 %0, %1, %2, %0;"
        : "+l"(reinterpret_cast<unsigned long long&>(d))
        : "l"(reinterpret_cast<const unsigned long long&>(a)),
          "l"(reinterpret_cast<const unsigned long long&>(b)));
}

// ---------------- setup kernels ----------------
__global__ void zero_init_kernel() {
    int i = blockIdx.x * blockDim.x + threadIdx.x;
    if (i < NN) g_cnt[i] = 0;
    if (i < GG) g_pool[i] = 0.f;
}

__global__ void count_kernel(const int* __restrict__ dst) {
    int i = blockIdx.x * blockDim.x + threadIdx.x;
    if (i < EE) atomicAdd(&g_cnt[dst[i]], 1);
}

__global__ void scan1_kernel() {
    __shared__ int s[256];
    int b = blockIdx.x, t = threadIdx.x;
    int idx = b * SCAN_CH + t;
    s[t] = (t < SCAN_CH && idx < NN) ? g_cnt[idx] : 0;
    __syncthreads();
    for (int off = 128; off; off >>= 1) {
        if (t < off) s[t] += s[t + off];
        __syncthreads();
    }
    if (t == 0) g_part[b] = s[0];
}

__global__ void scan2_kernel() {
    __shared__ int s[256];
    int t = threadIdx.x;
    s[t] = g_part[t];
    __syncthreads();
    int acc = s[t];
    for (int off = 1; off < 256; off <<= 1) {
        int v = 0;
        if (t >= off) v = s[t - off];
        __syncthreads();
        s[t] += v;
        __syncthreads();
    }
    g_base[t] = s[t] - acc;
}

__global__ void scan3_kernel() {
    __shared__ int s[256];
    int b = blockIdx.x, t = threadIdx.x;
    int idx = b * SCAN_CH + t;
    int c = (t < SCAN_CH && idx < NN) ? g_cnt[idx] : 0;
    s[t] = c;
    __syncthreads();
    int own = s[t];
    for (int off = 1; off < 256; off <<= 1) {
        int v = 0;
        if (t >= off) v = s[t - off];
        __syncthreads();
        s[t] += v;
        __syncthreads();
    }
    if (t < SCAN_CH && idx < NN) {
        g_rowptr[idx] = g_base[b] + s[t] - own;
        g_invdeg[idx] = 1.0f / (float)(c > 1 ? c : 1);
        g_cnt[idx] = 0;
    }
    if (b == 0 && t == 0) g_rowptr[NN] = EE;
}

__global__ void fill_kernel(const int* __restrict__ src,
                            const int* __restrict__ dst) {
    int i = blockIdx.x * blockDim.x + threadIdx.x;
    if (i >= EE) return;
    int d = dst[i];
    int pos = g_rowptr[d] + atomicAdd(&g_cnt[d], 1);
    g_colidx[pos] = src[i];
}

__global__ void transW_kernel(const float* __restrict__ wl,
                              const float* __restrict__ wr) {
    int idx = blockIdx.x * blockDim.x + threadIdx.x;
    if (idx >= LL * 2 * HH * HH) return;
    int l = idx / (2 * HH * HH);
    int rem = idx % (2 * HH * HH);
    int k = rem / HH;
    int o = rem % HH;
    float v = (k < HH) ? wl[(l * HH + o) * HH + k]
                       : wr[(l * HH + o) * HH + (k - HH)];
    g_Wt[idx] = v;
}

// ---------------- per-layer kernels ----------------
__global__ void agg_kernel(const float* __restrict__ x, int sel, int layer,
                           const float* __restrict__ gammaP,
                           const float* __restrict__ betaP) {
    int t = blockIdx.x * blockDim.x + threadIdx.x;
    int node = t >> 5;
    int lane = t & 31;
    if (node >= NN) return;
    const float4* h4 = (const float4*)sel_h(x, sel);
    float4 acc0 = make_float4(0.f, 0.f, 0.f, 0.f);
    float4 acc1 = make_float4(0.f, 0.f, 0.f, 0.f);
    int e0 = g_rowptr[node];
    int e1 = g_rowptr[node + 1];
    int j = e0;
    for (; j + 1 < e1; j += 2) {
        int s0 = g_colidx[j];
        int s1 = g_colidx[j + 1];
        float4 v0 = h4[s0 * 32 + lane];
        float4 v1 = h4[s1 * 32 + lane];
        acc0.x += v0.x; acc0.y += v0.y; acc0.z += v0.z; acc0.w += v0.w;
        acc1.x += v1.x; acc1.y += v1.y; acc1.z += v1.z; acc1.w += v1.w;
    }
    if (j < e1) {
        float4 v = h4[g_colidx[j] * 32 + lane];
        acc0.x += v.x; acc0.y += v.y; acc0.z += v.z; acc0.w += v.w;
    }
    acc0.x += acc1.x; acc0.y += acc1.y; acc0.z += acc1.z; acc0.w += acc1.w;
    float4 o = make_float4(0.f, 0.f, 0.f, 0.f);
    if (e1 > e0) {
        float inv = g_invdeg[node];
        float a0, b0, a1, b1, a2, b2, a3, b3;
        get_coef(layer, gammaP, betaP, lane * 4 + 0, a0, b0);
        get_coef(layer, gammaP, betaP, lane * 4 + 1, a1, b1);
        get_coef(layer, gammaP, betaP, lane * 4 + 2, a2, b2);
        get_coef(layer, gammaP, betaP, lane * 4 + 3, a3, b3);
        o = make_float4(fmaf(a0, acc0.x * inv, b0), fmaf(a1, acc0.y * inv, b1),
                        fmaf(a2, acc0.z * inv, b2), fmaf(a3, acc0.w * inv, b3));
    }
    ((float4*)g_agg)[node * 32 + lane] = o;
}

// fold prev affine into this layer's weights + bias; zero BN stats for this layer.
__global__ void prepareW_kernel(const float* __restrict__ bias, int layer,
                                const float* __restrict__ gammaP,
                                const float* __restrict__ betaP) {
    int b = blockIdx.x, tid = threadIdx.x;
    if (b < 128) {
        int idx = b * 256 + tid;
        int k = idx >> 7;
        float s = 1.f;
        if (k >= HH) {
            float a, bb;
            get_coef(layer, gammaP, betaP, k - HH, a, bb);
            s = a;
        }
        g_Ws[idx] = s * g_Wt[layer * 2 * HH * HH + idx];
    } else {
        __shared__ float cb[HH];
        if (tid < HH) {
            float a, bb;
            get_coef(layer, gammaP, betaP, tid, a, bb);
            cb[tid] = bb;
            g_sum[layer & 1][tid] = 0.f;
            g_sumsq[layer & 1][tid] = 0.f;
        }
        __syncthreads();
        if (tid < HH) {
            float s = bias[tid];
            const float* w = g_Wt + layer * 2 * HH * HH + HH * HH;
            for (int k = 0; k < HH; k++) s += cb[k] * w[k * HH + tid];
            g_bias[tid] = s;
        }
    }
}

// y = relu(agg @ Wl^T + bias' + h_raw @ Wr_scaled^T), fused BN column sums.
// 64x128 tile / 128 threads / 8x8 per thread; K=256 in 8 chunks of 32. occ 5.
__global__ void __launch_bounds__(128, 5)
gemm_kernel(const float* __restrict__ x, int sel, int outsel, int par) {
    __shared__ float As[32 * 64];    // A tile transposed: As[kk][row]
    __shared__ float Bs[32 * 128];   // W tile: Bs[kk][out]
    __shared__ float ssum[128];
    __shared__ float ssq[128];

    const int tid = threadIdx.x;
    const int tx = tid & 15;
    const int ty = tid >> 4;         // 0..7
    const int row0 = blockIdx.x * 64;

    const float* hin = sel_h(x, sel);
    float* yout = (outsel == 0) ? g_y0 : g_y1;

    float2 acc[4][8];   // row-pairs x 8 cols
    {
        float bc[8];
        #pragma unroll
        for (int j = 0; j < 4; j++) {
            bc[j]     = g_bias[tx * 4 + j];
            bc[4 + j] = g_bias[64 + tx * 4 + j];
        }
        #pragma unroll
        for (int i2 = 0; i2 < 4; i2++)
            #pragma unroll
            for (int j = 0; j < 8; j++) acc[i2][j] = make_float2(bc[j], bc[j]);
    }

    for (int chunk = 0; chunk < 8; chunk++) {
        // stage W tile: 32 k-rows x 128 outs (1024 float4s / 128 threads)
        {
            const float4* w4 = (const float4*)(g_Ws + chunk * 32 * HH);
            float4* bs4 = (float4*)Bs;
            #pragma unroll
            for (int i = 0; i < 8; i++) bs4[tid + i * 128] = w4[tid + i * 128];
        }
        // stage A tile: 64 rows x 32 k, transposed (512 float4s / 128 threads)
        {
            const float4* src4 = (const float4*)((chunk < 4) ? g_agg : hin);
            const int cseg = (chunk & 3) * 8;
            #pragma unroll
            for (int i = 0; i < 4; i++) {
                int idx = tid + i * 128;
                int r = idx >> 3, seg = idx & 7;
                int row = row0 + r;
                float4 v = make_float4(0.f, 0.f, 0.f, 0.f);
                if (row < NN) v = src4[row * 32 + cseg + seg];
                As[(seg * 4 + 0) * 64 + r] = v.x;
                As[(seg * 4 + 1) * 64 + r] = v.y;
                As[(seg * 4 + 2) * 64 + r] = v.z;
                As[(seg * 4 + 3) * 64 + r] = v.w;
            }
        }
        __syncthreads();
        #pragma unroll 16
        for (int kk = 0; kk < 32; kk++) {
            float4 a0 = *(const float4*)&As[kk * 64 + ty * 4];
            float4 a1 = *(const float4*)&As[kk * 64 + 32 + ty * 4];
            float4 b0 = *(const float4*)&Bs[kk * 128 + tx * 4];
            float4 b1 = *(const float4*)&Bs[kk * 128 + 64 + tx * 4];
            float2 ap[4] = {{a0.x, a0.y}, {a0.z, a0.w}, {a1.x, a1.y}, {a1.z, a1.w}};
            float  bj[8] = {b0.x, b0.y, b0.z, b0.w, b1.x, b1.y, b1.z, b1.w};
            #pragma unroll
            for (int j = 0; j < 8; j++) {
                float2 bb = make_float2(bj[j], bj[j]);
                #pragma unroll
                for (int i2 = 0; i2 < 4; i2++) ffma2(acc[i2][j], ap[i2], bb);
            }
        }
        __syncthreads();
    }

    // epilogue: relu, store, BN column sums
    float csum[8], csq[8];
    #pragma unroll
    for (int j = 0; j < 8; j++) { csum[j] = 0.f; csq[j] = 0.f; }
    #pragma unroll
    for (int i2 = 0; i2 < 4; i2++) {
        int rbase = (i2 < 2) ? (row0 + ty * 4 + i2 * 2)
                             : (row0 + 32 + ty * 4 + (i2 - 2) * 2);
        #pragma unroll
        for (int half = 0; half < 2; half++) {
            int r = rbase + half;
            if (r < NN) {
                float v[8];
                #pragma unroll
                for (int j = 0; j < 8; j++) {
                    float raw = half ? acc[i2][j].y : acc[i2][j].x;
                    v[j] = fmaxf(raw, 0.f);
                    csum[j] += v[j];
                    csq[j]  += v[j] * v[j];
                }
                float4* y4 = (float4*)(yout + r * HH);
                y4[tx]      = make_float4(v[0], v[1], v[2], v[3]);
                y4[16 + tx] = make_float4(v[4], v[5], v[6], v[7]);
            }
        }
    }
    ssum[tid] = 0.f; ssq[tid] = 0.f;
    __syncthreads();
    #pragma unroll
    for (int j = 0; j < 4; j++) {
        atomicAdd(&ssum[tx * 4 + j],      csum[j]);
        atomicAdd(&ssq[tx * 4 + j],       csq[j]);
        atomicAdd(&ssum[64 + tx * 4 + j], csum[4 + j]);
        atomicAdd(&ssq[64 + tx * 4 + j],  csq[4 + j]);
    }
    __syncthreads();
    atomicAdd(&g_sum[par][tid],   ssum[tid]);
    atomicAdd(&g_sumsq[par][tid], ssq[tid]);
}

// fold last layer's affine into the FC: fcs = a .* fcw ; c0 = sum(b .* fcw)
__global__ void fcprep_kernel(const float* __restrict__ fcw,
                              const float* __restrict__ gammaP,
                              const float* __restrict__ betaP) {
    __shared__ float red[128];
    int c = threadIdx.x;
    float w = fcw[c];
    float a, b;
    get_coef(LL, gammaP, betaP, c, a, b);
    g_fcs[c] = a * w;
    red[c] = b * w;
    __syncthreads();
    for (int off = 64; off; off >>= 1) {
        if (c < off) red[c] += red[c + off];
        __syncthreads();
    }
    if (c == 0) g_c0 = red[0];
}

__global__ void pool_kernel(const int* __restrict__ batch) {
    int t = blockIdx.x * blockDim.x + threadIdx.x;
    int node = t >> 5;
    int lane = t & 31;
    if (node >= NN) return;
    float4 v = ((const float4*)g_y0)[node * 32 + lane];
    float4 w = ((const float4*)g_fcs)[lane];
    float s = v.x * w.x + v.y * w.y + v.z * w.z + v.w * w.w;
    #pragma unroll
    for (int off = 16; off; off >>= 1) s += __shfl_down_sync(0xffffffffu, s, off);
    if (lane == 0) atomicAdd(&g_pool[batch[node]], s + g_c0);
}

__global__ void final_kernel(const float* __restrict__ fcb, float* __restrict__ out) {
    int g = threadIdx.x;
    if (g < GG) {
        float z = g_pool[g] + fcb[0];
        out[g] = 1.0f / (1.0f + expf(-z));
    }
}

// ---------------- launch ----------------
extern "C" void kernel_launch(void* const* d_in, const int* in_sizes, int n_in,
                              void* d_out, int out_size) {
    const float* x       = (const float*)d_in[0];
    const int*   ei      = (const int*)d_in[1];
    const int*   src     = ei;
    const int*   dst     = ei + EE;
    const int*   batch   = (const int*)d_in[3];
    const float* lin_l_w = (const float*)d_in[4];
    const float* lin_l_b = (const float*)d_in[5];
    const float* lin_r_w = (const float*)d_in[6];
    const float* gamma   = (const float*)d_in[7];
    const float* beta    = (const float*)d_in[8];
    const float* fcw     = (const float*)d_in[9];
    const float* fcb     = (const float*)d_in[10];
    float*       out     = (float*)d_out;

    zero_init_kernel<<<(NN + 255) / 256, 256>>>();
    count_kernel<<<(EE + 255) / 256, 256>>>(dst);
    scan1_kernel<<<256, 256>>>();
    scan2_kernel<<<1, 256>>>();
    scan3_kernel<<<256, 256>>>();
    fill_kernel<<<(EE + 255) / 256, 256>>>(src, dst);
    transW_kernel<<<(LL * 2 * HH * HH + 255) / 256, 256>>>(lin_l_w, lin_r_w);

    for (int l = 0; l < LL; l++) {
        int sel    = (l == 0) ? 0 : ((l == 1) ? 1 : 2);   // x, g_y0, g_y1
        int outsel = (l == 1) ? 1 : 0;                    // y0, y1, y0
        const float* gp = gamma + (l > 0 ? (l - 1) * HH : 0);
        const float* bp = beta  + (l > 0 ? (l - 1) * HH : 0);
        agg_kernel<<<(NN * 32 + 255) / 256, 256>>>(x, sel, l, gp, bp);
        prepareW_kernel<<<129, 256>>>(lin_l_b + l * HH, l, gp, bp);
        gemm_kernel<<<(NN + 63) / 64, 128>>>(x, sel, outsel, l & 1);
    }

    fcprep_kernel<<<1, 128>>>(fcw, gamma + 2 * HH, beta + 2 * HH);
    pool_kernel<<<(NN * 32 + 255) / 256, 256>>>(batch);
    final_kernel<<<1, 64>>>(fcb, out);
}